// round 8
// baseline (speedup 1.0000x reference)
#include <cuda_runtime.h>
#include <cstdint>

// Batched outer product: out[i, j*K + l] = x[i,j] * y[i,l]
// n=4096, m=256, k=256 → out row = 65536 f32 = 16384 float4.
// Pure store-bandwidth kernel (~1.07 GB written) at the HBM write wall.
// R7: persistent grid-stride (grid = 148*8 = 1184) to remove wave
// transitions + drain tail. Otherwise identical to best config:
// smem-staged x (double-buffered), float4 .cs streaming stores, full unroll.

static constexpr int M = 256;   // x row length
static constexpr int K = 256;   // y row length
static constexpr int ROW_F4 = (M * K) / 4;  // 16384 float4 per output row
static constexpr int GRID = 148 * 8;        // one full occupancy wave

__global__ __launch_bounds__(256, 8)
void omul_kernel(const float* __restrict__ x,
                 const float* __restrict__ y,
                 float4* __restrict__ out,
                 int n_rows)
{
    __shared__ float xs[2][M];

    const int t = threadIdx.x;

    int buf = 0;
    for (int row = blockIdx.x; row < n_rows; row += GRID, buf ^= 1) {
        // Stage this row's x into the idle smem buffer (no leading barrier
        // needed: previous iteration's consumers read the other buffer and
        // the trailing __syncthreads below ordered them before this write).
        xs[buf][t] = x[(size_t)row * M + t];
        const float4 yv =
            reinterpret_cast<const float4*>(y + (size_t)row * K)[t & 63];
        __syncthreads();

        float4* o = out + (size_t)row * ROW_F4;

        #pragma unroll
        for (int i = 0; i < 64; i++) {
            const int idx = i * 256 + t;
            const float xv = xs[buf][idx >> 6];   // broadcast, conflict-free
            float4 r;
            r.x = xv * yv.x;
            r.y = xv * yv.y;
            r.z = xv * yv.z;
            r.w = xv * yv.w;
            __stcs(&o[idx], r);                   // evict-first streaming store
        }
        __syncthreads();
    }
}

extern "C" void kernel_launch(void* const* d_in, const int* in_sizes, int n_in,
                              void* d_out, int out_size)
{
    const float* x = (const float*)d_in[0];
    const float* y = (const float*)d_in[1];
    float4* out = (float4*)d_out;

    const int n = in_sizes[0] / M;  // 4096 rows
    omul_kernel<<<GRID, 256>>>(x, y, out, n);
}

// round 10
// speedup vs baseline: 1.1243x; 1.1243x over previous
#include <cuda_runtime.h>
#include <cstdint>

// Batched outer product: out[i, j*K + l] = x[i,j] * y[i,l]
// n=4096, m=256, k=256 → out row = 65536 f32 = 16384 float4.
// Pure store-bandwidth kernel (~1.07 GB written) at the HBM write wall.
// R9: same structure as champion (smem x, float4 .cs stores, 1 row/CTA,
// HW-scheduled grid=4096) but block=512 / occ 4: fewer input-load ramps,
// deeper store MLP per CTA.

static constexpr int M = 256;   // x row length
static constexpr int K = 256;   // y row length
static constexpr int ROW_F4 = (M * K) / 4;  // 16384 float4 per output row
static constexpr int BLK = 512;

__global__ __launch_bounds__(BLK, 4)
void omul_kernel(const float* __restrict__ x,
                 const float* __restrict__ y,
                 float4* __restrict__ out)
{
    __shared__ float xs[M];

    const int row = blockIdx.x;
    const int t   = threadIdx.x;

    // Stage x row (first 256 threads), y float4 chunk fixed per thread:
    // (idx & 63) == (t & 63) for all iterations.
    if (t < M) xs[t] = x[(size_t)row * M + t];
    const float4 yv = reinterpret_cast<const float4*>(y + (size_t)row * K)[t & 63];
    __syncthreads();

    float4* o = out + (size_t)row * ROW_F4;

    // 32 iterations × 512 threads = 16384 float4 stores, fully coalesced.
    #pragma unroll
    for (int i = 0; i < 32; i++) {
        const int idx = i * BLK + t;
        const float xv = xs[idx >> 6];        // smem broadcast, conflict-free
        float4 r;
        r.x = xv * yv.x;
        r.y = xv * yv.y;
        r.z = xv * yv.z;
        r.w = xv * yv.w;
        __stcs(&o[idx], r);                   // evict-first streaming store
    }
}

extern "C" void kernel_launch(void* const* d_in, const int* in_sizes, int n_in,
                              void* d_out, int out_size)
{
    const float* x = (const float*)d_in[0];
    const float* y = (const float*)d_in[1];
    float4* out = (float4*)d_out;

    const int n = in_sizes[0] / M;  // 4096 rows
    omul_kernel<<<n, BLK>>>(x, y, out);
}

// round 11
// speedup vs baseline: 1.1553x; 1.0275x over previous
#include <cuda_runtime.h>
#include <cstdint>

// Batched outer product: out[i, j*K + l] = x[i,j] * y[i,l]
// n=4096, m=256, k=256 → out row = 65536 f32 = 16384 float4.
// Pure store-bandwidth kernel (~1.07 GB written) at the HBM write wall.
// R11: champion structure (smem x, float4 .cs stores, 1 row/CTA, grid=4096)
// with block=1024 / occ 2 — continue the block-size↑ trend from R10's win.

static constexpr int M = 256;   // x row length
static constexpr int K = 256;   // y row length
static constexpr int ROW_F4 = (M * K) / 4;  // 16384 float4 per output row
static constexpr int BLK = 1024;

__global__ __launch_bounds__(BLK, 2)
void omul_kernel(const float* __restrict__ x,
                 const float* __restrict__ y,
                 float4* __restrict__ out)
{
    __shared__ float xs[M];

    const int row = blockIdx.x;
    const int t   = threadIdx.x;

    // Stage x row (first 256 threads); y float4 chunk fixed per thread:
    // (idx & 63) == (t & 63) for all iterations.
    if (t < M) xs[t] = x[(size_t)row * M + t];
    const float4 yv = reinterpret_cast<const float4*>(y + (size_t)row * K)[t & 63];
    __syncthreads();

    float4* o = out + (size_t)row * ROW_F4;

    // 16 iterations × 1024 threads = 16384 float4 stores, fully coalesced.
    #pragma unroll
    for (int i = 0; i < 16; i++) {
        const int idx = i * BLK + t;
        const float xv = xs[idx >> 6];        // smem broadcast, conflict-free
        float4 r;
        r.x = xv * yv.x;
        r.y = xv * yv.y;
        r.z = xv * yv.z;
        r.w = xv * yv.w;
        __stcs(&o[idx], r);                   // evict-first streaming store
    }
}

extern "C" void kernel_launch(void* const* d_in, const int* in_sizes, int n_in,
                              void* d_out, int out_size)
{
    const float* x = (const float*)d_in[0];
    const float* y = (const float*)d_in[1];
    float4* out = (float4*)d_out;

    const int n = in_sizes[0] / M;  // 4096 rows
    omul_kernel<<<n, BLK>>>(x, y, out);
}